// round 2
// baseline (speedup 1.0000x reference)
#include <cuda_runtime.h>

#define NN 100000
#define NE 1280000
#define FD 64
#define NG 1000
#define BN_EPS 1e-5f

// ---------------- device scratch (allocation-free rule: __device__ globals) ----
__device__ float g_dinv[NN];                 // degree -> rsqrt(degree)
__device__ float g_t[(size_t)NN * FD];       // transformed features (pre-message)
__device__ float g_agg[(size_t)NN * FD];     // aggregated features
__device__ float g_Wp[FD * FD];              // BN-folded weight
__device__ float g_crow[FD];                 // BN-folded row constant
__device__ float g_stats[6 * FD];            // s1 ss1 | s2 ss2 | s3 ss3
__device__ float g_gsum[NG * FD];            // per-graph sums
__device__ float g_gcnt[NG];                 // per-graph counts
__device__ float g_Woutp[FD * 2];            // BN3-folded output weight
__device__ float g_cb[2];                    // folded output bias
__device__ int   g_is64;                     // index dtype flag (detected from data)

// ---------------- dtype detection: int64 little-endian => odd 32-bit words all 0
__global__ void detect_kernel(const int* __restrict__ ei) {
    __shared__ int nz;
    if (threadIdx.x == 0) nz = 0;
    __syncthreads();
    int local = 0;
    for (int i = threadIdx.x; i < 4096; i += blockDim.x)
        if (ei[2 * i + 1] != 0) local = 1;
    if (local) nz = 1;
    __syncthreads();
    if (threadIdx.x == 0) g_is64 = (nz == 0) ? 1 : 0;
}

// ---------------- zero/seed accumulators (deg starts at 1.0 == self loop)
__global__ void init_kernel() {
    int i = blockIdx.x * blockDim.x + threadIdx.x;
    if (i < NN) g_dinv[i] = 1.0f;
    if (i < 6 * FD) g_stats[i] = 0.0f;
    if (i < NG * FD) g_gsum[i] = 0.0f;
    if (i < NG) g_gcnt[i] = 0.0f;
}

// ---------------- degree over edge targets
__global__ void deg_kernel(const int* __restrict__ ei) {
    int e = blockIdx.x * blockDim.x + threadIdx.x;
    if (e >= NE) return;
    int c = g_is64 ? ei[2 * (NE + e)] : ei[NE + e];
    atomicAdd(&g_dinv[c], 1.0f);
}

__global__ void rsqrt_kernel() {
    int i = blockIdx.x * blockDim.x + threadIdx.x;
    if (i < NN) g_dinv[i] = rsqrtf(g_dinv[i]);
}

// ---------------- per-feature sum / sumsq (optionally relu(in + bias))
__global__ void bn_stats_kernel(const float* __restrict__ xin, int use_agg,
                                const float* __restrict__ bias, int dorelu, int soff) {
    const float* __restrict__ src = use_agg ? g_agg : xin;
    int f   = threadIdx.x & 63;
    int sub = threadIdx.x >> 6;
    float bs = dorelu ? bias[f] : 0.0f;
    float s = 0.0f, ss = 0.0f;
    for (int n = blockIdx.x * 4 + sub; n < NN; n += gridDim.x * 4) {
        float v = src[(size_t)n * FD + f];
        if (dorelu) v = fmaxf(v + bs, 0.0f);
        s += v; ss += v * v;
    }
    atomicAdd(&g_stats[soff + f], s);
    atomicAdd(&g_stats[soff + 64 + f], ss);
}

// ---------------- fold BN(gamma,beta, stats) into W:  Wp = diag(a) W, crow = c @ W
__global__ void prep_kernel(const float* __restrict__ gg, const float* __restrict__ bb,
                            const float* __restrict__ W, int soff) {
    __shared__ float a[FD], c[FD];
    int f = threadIdx.x;
    float m = g_stats[soff + f] * (1.0f / NN);
    float v = fmaxf(g_stats[soff + 64 + f] * (1.0f / NN) - m * m, 0.0f);
    float af = gg[f] * rsqrtf(v + BN_EPS);
    a[f] = af;
    c[f] = bb[f] - m * af;
    __syncthreads();
    float cr = 0.0f;
    for (int i = 0; i < FD; i++) {
        float w = W[i * FD + f];
        g_Wp[i * FD + f] = a[i] * w;
        cr += c[i] * w;
    }
    g_crow[f] = cr;
}

// ---------------- t = prologue(in) @ Wp + crow  (prologue = relu(in + bias) if dorelu)
__global__ void gemm_kernel(const float* __restrict__ xin, int use_agg,
                            const float* __restrict__ bias, int dorelu) {
    __shared__ float sIn[16 * FD];
    __shared__ float sW[FD * FD];
    const float* __restrict__ src = use_agg ? g_agg : xin;
    int tid = threadIdx.x;
    for (int i = tid; i < FD * FD; i += 256) sW[i] = g_Wp[i];
    int base = blockIdx.x * 16;
    for (int i = tid; i < 16 * FD; i += 256) {
        int r = i >> 6, k = i & 63;
        float v = src[(size_t)(base + r) * FD + k];
        if (dorelu) v = fmaxf(v + bias[k], 0.0f);
        sIn[i] = v;
    }
    __syncthreads();
    int r = tid >> 4, tc = tid & 15;
    float4 acc = make_float4(0.f, 0.f, 0.f, 0.f);
    const float4* sW4 = (const float4*)sW;
#pragma unroll
    for (int k = 0; k < FD; k++) {
        float xv = sIn[r * FD + k];
        float4 w = sW4[k * 16 + tc];
        acc.x += xv * w.x; acc.y += xv * w.y; acc.z += xv * w.z; acc.w += xv * w.w;
    }
    float4 cr = ((const float4*)g_crow)[tc];
    acc.x += cr.x; acc.y += cr.y; acc.z += cr.z; acc.w += cr.w;
    ((float4*)g_t)[(size_t)(base + r) * 16 + tc] = acc;
}

// ---------------- self-loop term also initializes agg:  agg = t * dinv^2
__global__ void selfloop_kernel() {
    int i = blockIdx.x * blockDim.x + threadIdx.x;   // over NN*16 float4
    if (i >= NN * 16) return;
    int n = i >> 4;
    float d = g_dinv[n];
    float s = d * d;
    float4 v = ((const float4*)g_t)[i];
    v.x *= s; v.y *= s; v.z *= s; v.w *= s;
    ((float4*)g_agg)[i] = v;
}

// ---------------- edge scatter: warp per edge, lane = 2 features (coalesced atomics)
__global__ void scatter_kernel(const int* __restrict__ ei) {
    int lane   = threadIdx.x & 31;
    int warp   = (blockIdx.x * blockDim.x + threadIdx.x) >> 5;
    int nwarps = (gridDim.x * blockDim.x) >> 5;
    int is64 = g_is64;
    for (int e = warp; e < NE; e += nwarps) {
        int r, c;
        if (is64) { r = ei[2 * e]; c = ei[2 * (NE + e)]; }
        else      { r = ei[e];     c = ei[NE + e]; }
        float nrm = g_dinv[r] * g_dinv[c];
        float2 v = ((const float2*)g_t)[(size_t)r * 32 + lane];
        atomicAdd(&g_agg[(size_t)c * FD + 2 * lane],     v.x * nrm);
        atomicAdd(&g_agg[(size_t)c * FD + 2 * lane + 1], v.y * nrm);
    }
}

// ---------------- y = relu(agg + b2): global BN stats + per-graph sums/counts
__global__ void pool_kernel(const float* __restrict__ bias, const int* __restrict__ batch) {
    int f   = threadIdx.x & 63;
    int sub = threadIdx.x >> 6;
    int is64 = g_is64;
    float bs = bias[f];
    float s = 0.0f, ss = 0.0f;
    for (int n = blockIdx.x * 4 + sub; n < NN; n += gridDim.x * 4) {
        float v = fmaxf(g_agg[(size_t)n * FD + f] + bs, 0.0f);
        s += v; ss += v * v;
        int b = is64 ? batch[2 * n] : batch[n];
        atomicAdd(&g_gsum[b * FD + f], v);
        if (f == 0) atomicAdd(&g_gcnt[b], 1.0f);
    }
    atomicAdd(&g_stats[256 + f], s);
    atomicAdd(&g_stats[320 + f], ss);
}

// ---------------- fold BN3 into Wout:  Woutp = diag(a3) Wout, cb = c3 @ Wout + bout
__global__ void prep3_kernel(const float* __restrict__ gg, const float* __restrict__ bb,
                             const float* __restrict__ Wout, const float* __restrict__ bout) {
    __shared__ float c[FD];
    int f = threadIdx.x;
    float m = g_stats[256 + f] * (1.0f / NN);
    float v = fmaxf(g_stats[320 + f] * (1.0f / NN) - m * m, 0.0f);
    float af = gg[f] * rsqrtf(v + BN_EPS);
    c[f] = bb[f] - m * af;
    g_Woutp[f * 2]     = af * Wout[f * 2];
    g_Woutp[f * 2 + 1] = af * Wout[f * 2 + 1];
    __syncthreads();
    if (f < 2) {
        float acc = bout[f];
        for (int i = 0; i < FD; i++) acc += c[i] * Wout[i * 2 + f];
        g_cb[f] = acc;
    }
}

// ---------------- out[g] = (gsum[g]/max(cnt,1) .* a3 + c3) @ Wout + bout
__global__ void final_kernel(float* __restrict__ out, const float* __restrict__ bout) {
    int g = blockIdx.x * blockDim.x + threadIdx.x;
    if (g >= NG) return;
    float cnt = g_gcnt[g];
    if (cnt > 0.0f) {
        float inv = 1.0f / cnt;
        float a0 = g_cb[0], a1 = g_cb[1];
#pragma unroll 8
        for (int f = 0; f < FD; f++) {
            float p = g_gsum[g * FD + f] * inv;
            a0 += p * g_Woutp[f * 2];
            a1 += p * g_Woutp[f * 2 + 1];
        }
        out[g * 2] = a0; out[g * 2 + 1] = a1;
    } else {
        out[g * 2] = bout[0]; out[g * 2 + 1] = bout[1];
    }
}

extern "C" void kernel_launch(void* const* d_in, const int* in_sizes, int n_in,
                              void* d_out, int out_size) {
    const float* x       = (const float*)d_in[0];
    const int*   ei      = (const int*)d_in[1];   // int32 or int64 (detected)
    const int*   batch   = (const int*)d_in[2];
    const float* bn_in_g = (const float*)d_in[3];
    const float* bn_in_b = (const float*)d_in[4];
    const float* W1      = (const float*)d_in[5];
    const float* b1      = (const float*)d_in[6];
    const float* g1      = (const float*)d_in[7];
    const float* be1     = (const float*)d_in[8];
    const float* W2      = (const float*)d_in[9];
    const float* b2      = (const float*)d_in[10];
    const float* g2      = (const float*)d_in[11];
    const float* be2     = (const float*)d_in[12];
    const float* Wout    = (const float*)d_in[13];
    const float* bout    = (const float*)d_in[14];
    float* out = (float*)d_out;

    detect_kernel<<<1, 256>>>(ei);
    init_kernel<<<(NN + 255) / 256, 256>>>();
    deg_kernel<<<(NE + 255) / 256, 256>>>(ei);
    rsqrt_kernel<<<(NN + 255) / 256, 256>>>();

    // conv1: BN(x) folded into W1
    bn_stats_kernel<<<512, 256>>>(x, 0, x, 0, 0);
    prep_kernel<<<1, 64>>>(bn_in_g, bn_in_b, W1, 0);
    gemm_kernel<<<NN / 16, 256>>>(x, 0, x, 0);
    selfloop_kernel<<<(NN * 16 + 255) / 256, 256>>>();
    scatter_kernel<<<2048, 256>>>(ei);

    // conv2: BN(relu(agg1 + b1)) folded into W2
    bn_stats_kernel<<<512, 256>>>(x, 1, b1, 1, 128);
    prep_kernel<<<1, 64>>>(g1, be1, W2, 128);
    gemm_kernel<<<NN / 16, 256>>>(x, 1, b1, 1);
    selfloop_kernel<<<(NN * 16 + 255) / 256, 256>>>();
    scatter_kernel<<<2048, 256>>>(ei);

    // pool + BN3 folded into Wout
    pool_kernel<<<512, 256>>>(b2, batch);
    prep3_kernel<<<1, 64>>>(g2, be2, Wout, bout);
    final_kernel<<<4, 256>>>(out, bout);
}

// round 3
// speedup vs baseline: 1.2560x; 1.2560x over previous
#include <cuda_runtime.h>

#define NN 100000
#define NE 1280000
#define FD 64
#define NG 1000
#define BN_EPS 1e-5f
#define SCAN_CH 1024
#define SCAN_NB ((NN + SCAN_CH - 1) / SCAN_CH)   // 98

// ---------------- device scratch (allocation-free rule: __device__ globals) ----
__device__ int   g_deg[NN];                  // in-degree (excl. self loop)
__device__ float g_dinv[NN];                 // rsqrt(deg+1)
__device__ float g_t[(size_t)NN * FD];       // transformed features (pre-message)
__device__ float g_agg[(size_t)NN * FD];     // aggregated features
__device__ float g_Wp[FD * FD];              // BN-folded weight
__device__ float g_crow[FD];                 // BN-folded row constant
__device__ float g_stats[6 * FD];            // s1 ss1 | s2 ss2 | s3 ss3
__device__ float g_gsum[NG * FD];            // per-graph sums
__device__ float g_gcnt[NG];                 // per-graph counts
__device__ float g_Woutp[FD * 2];            // BN3-folded output weight
__device__ float g_cb[2];                    // folded output bias
__device__ int   g_is64;                     // index dtype flag (detected from data)
// CSR (sorted by destination)
__device__ int   g_rowptr[NN + 1];
__device__ int   g_fill[NN];
__device__ int   g_csr_src[NE];
__device__ float g_csr_nrm[NE];
__device__ int   g_bsum[SCAN_NB];
__device__ int   g_boff[SCAN_NB];

// ---------------- dtype detection: int64 little-endian => odd 32-bit words all 0
__global__ void detect_kernel(const int* __restrict__ ei) {
    __shared__ int nz;
    if (threadIdx.x == 0) nz = 0;
    __syncthreads();
    int local = 0;
    for (int i = threadIdx.x; i < 4096; i += blockDim.x)
        if (ei[2 * i + 1] != 0) local = 1;
    if (local) nz = 1;
    __syncthreads();
    if (threadIdx.x == 0) g_is64 = (nz == 0) ? 1 : 0;
}

__global__ void init_kernel() {
    int i = blockIdx.x * blockDim.x + threadIdx.x;
    if (i < NN) g_deg[i] = 0;
    if (i < 6 * FD) g_stats[i] = 0.0f;
    if (i < NG * FD) g_gsum[i] = 0.0f;
    if (i < NG) g_gcnt[i] = 0.0f;
}

// ---------------- in-degree over edge targets
__global__ void deg_kernel(const int* __restrict__ ei) {
    int e = blockIdx.x * blockDim.x + threadIdx.x;
    if (e >= NE) return;
    int c = g_is64 ? ei[2 * (NE + e)] : ei[NE + e];
    atomicAdd(&g_deg[c], 1);
}

__global__ void rsqrt_kernel() {
    int i = blockIdx.x * blockDim.x + threadIdx.x;
    if (i < NN) g_dinv[i] = rsqrtf((float)g_deg[i] + 1.0f);
}

// ---------------- two-level exclusive scan of g_deg -> g_rowptr  ------------
__global__ void scanA_kernel() {            // per-chunk sums
    __shared__ int sh[256];
    int b = blockIdx.x, t = threadIdx.x;
    int base = b * SCAN_CH + t * 4;
    int s = 0;
#pragma unroll
    for (int k = 0; k < 4; k++) {
        int i = base + k;
        if (i < NN) s += g_deg[i];
    }
    sh[t] = s;
    __syncthreads();
    for (int off = 128; off > 0; off >>= 1) {
        if (t < off) sh[t] += sh[t + off];
        __syncthreads();
    }
    if (t == 0) g_bsum[b] = sh[0];
}

__global__ void scanB_kernel() {            // exclusive scan of 98 chunk sums
    if (threadIdx.x == 0) {
        int acc = 0;
        for (int b = 0; b < SCAN_NB; b++) { g_boff[b] = acc; acc += g_bsum[b]; }
        g_rowptr[NN] = acc;                 // == NE
    }
}

__global__ void scanC_kernel() {            // per-chunk exclusive scan + offsets
    __shared__ int sh[257];
    int b = blockIdx.x, t = threadIdx.x;
    int base = b * SCAN_CH + t * 4;
    int v[4]; int s = 0;
#pragma unroll
    for (int k = 0; k < 4; k++) {
        int i = base + k;
        v[k] = (i < NN) ? g_deg[i] : 0;
        s += v[k];
    }
    sh[t + 1] = s;
    if (t == 0) sh[0] = 0;
    __syncthreads();
    // Hillis-Steele inclusive scan over sh[1..256]
    for (int off = 1; off < 256; off <<= 1) {
        int val = (t + 1 > off) ? sh[t + 1 - off] : 0;
        __syncthreads();
        sh[t + 1] += val;
        __syncthreads();
    }
    int run = g_boff[b] + sh[t];
#pragma unroll
    for (int k = 0; k < 4; k++) {
        int i = base + k;
        if (i < NN) { g_rowptr[i] = run; g_fill[i] = run; run += v[k]; }
    }
}

// ---------------- edge placement into CSR, with precomputed norm ------------
__global__ void place_kernel(const int* __restrict__ ei) {
    int e = blockIdx.x * blockDim.x + threadIdx.x;
    if (e >= NE) return;
    int r, c;
    if (g_is64) { r = ei[2 * e]; c = ei[2 * (NE + e)]; }
    else        { r = ei[e];     c = ei[NE + e]; }
    int pos = atomicAdd(&g_fill[c], 1);
    g_csr_src[pos] = r;
    g_csr_nrm[pos] = g_dinv[r] * g_dinv[c];
}

// ---------------- per-feature sum / sumsq (optionally relu(in + bias))
__global__ void bn_stats_kernel(const float* __restrict__ xin, int use_agg,
                                const float* __restrict__ bias, int dorelu, int soff) {
    const float* __restrict__ src = use_agg ? g_agg : xin;
    int f   = threadIdx.x & 63;
    int sub = threadIdx.x >> 6;
    float bs = dorelu ? bias[f] : 0.0f;
    float s = 0.0f, ss = 0.0f;
    for (int n = blockIdx.x * 4 + sub; n < NN; n += gridDim.x * 4) {
        float v = src[(size_t)n * FD + f];
        if (dorelu) v = fmaxf(v + bs, 0.0f);
        s += v; ss += v * v;
    }
    atomicAdd(&g_stats[soff + f], s);
    atomicAdd(&g_stats[soff + 64 + f], ss);
}

// ---------------- fold BN(gamma,beta, stats) into W:  Wp = diag(a) W, crow = c @ W
__global__ void prep_kernel(const float* __restrict__ gg, const float* __restrict__ bb,
                            const float* __restrict__ W, int soff) {
    __shared__ float a[FD], c[FD];
    int f = threadIdx.x;
    float m = g_stats[soff + f] * (1.0f / NN);
    float v = fmaxf(g_stats[soff + 64 + f] * (1.0f / NN) - m * m, 0.0f);
    float af = gg[f] * rsqrtf(v + BN_EPS);
    a[f] = af;
    c[f] = bb[f] - m * af;
    __syncthreads();
    float cr = 0.0f;
    for (int i = 0; i < FD; i++) {
        float w = W[i * FD + f];
        g_Wp[i * FD + f] = a[i] * w;
        cr += c[i] * w;
    }
    g_crow[f] = cr;
}

// ---------------- t = prologue(in) @ Wp + crow  (prologue = relu(in + bias))
__global__ void gemm_kernel(const float* __restrict__ xin, int use_agg,
                            const float* __restrict__ bias, int dorelu) {
    __shared__ float sIn[16 * FD];
    __shared__ float sW[FD * FD];
    const float* __restrict__ src = use_agg ? g_agg : xin;
    int tid = threadIdx.x;
    for (int i = tid; i < FD * FD; i += 256) sW[i] = g_Wp[i];
    int base = blockIdx.x * 16;
    for (int i = tid; i < 16 * FD; i += 256) {
        int r = i >> 6, k = i & 63;
        float v = src[(size_t)(base + r) * FD + k];
        if (dorelu) v = fmaxf(v + bias[k], 0.0f);
        sIn[i] = v;
    }
    __syncthreads();
    int r = tid >> 4, tc = tid & 15;
    float4 acc = make_float4(0.f, 0.f, 0.f, 0.f);
    const float4* sW4 = (const float4*)sW;
#pragma unroll
    for (int k = 0; k < FD; k++) {
        float xv = sIn[r * FD + k];
        float4 w = sW4[k * 16 + tc];
        acc.x += xv * w.x; acc.y += xv * w.y; acc.z += xv * w.z; acc.w += xv * w.w;
    }
    float4 cr = ((const float4*)g_crow)[tc];
    acc.x += cr.x; acc.y += cr.y; acc.z += cr.z; acc.w += cr.w;
    ((float4*)g_t)[(size_t)(base + r) * 16 + tc] = acc;
}

// ---------------- CSR gather conv: warp per node, lane = 2 features ---------
// agg[n] = t[n]*dinv[n]^2 + sum_{e: dst=n} t[src_e] * nrm_e
__global__ void gather_kernel() {
    int lane = threadIdx.x & 31;
    int n = (blockIdx.x * blockDim.x + threadIdx.x) >> 5;
    if (n >= NN) return;
    float d = g_dinv[n];
    float s = d * d;
    float2 acc = ((const float2*)g_t)[(size_t)n * 32 + lane];
    acc.x *= s; acc.y *= s;
    int j = g_rowptr[n], end = g_rowptr[n + 1];
    if (j < end) {
        int r0 = g_csr_src[j];
        float w0 = g_csr_nrm[j];
        for (; j < end; j++) {
            int r = r0; float w = w0;
            if (j + 1 < end) { r0 = g_csr_src[j + 1]; w0 = g_csr_nrm[j + 1]; }
            float2 v = ((const float2*)g_t)[(size_t)r * 32 + lane];
            acc.x += v.x * w; acc.y += v.y * w;
        }
    }
    ((float2*)g_agg)[(size_t)n * 32 + lane] = acc;
}

// ---------------- y = relu(agg + b2): global BN stats + per-graph sums/counts
__global__ void pool_kernel(const float* __restrict__ bias, const int* __restrict__ batch) {
    int f   = threadIdx.x & 63;
    int sub = threadIdx.x >> 6;
    int is64 = g_is64;
    float bs = bias[f];
    float s = 0.0f, ss = 0.0f;
    for (int n = blockIdx.x * 4 + sub; n < NN; n += gridDim.x * 4) {
        float v = fmaxf(g_agg[(size_t)n * FD + f] + bs, 0.0f);
        s += v; ss += v * v;
        int b = is64 ? batch[2 * n] : batch[n];
        atomicAdd(&g_gsum[b * FD + f], v);
        if (f == 0) atomicAdd(&g_gcnt[b], 1.0f);
    }
    atomicAdd(&g_stats[256 + f], s);
    atomicAdd(&g_stats[320 + f], ss);
}

// ---------------- fold BN3 into Wout:  Woutp = diag(a3) Wout, cb = c3 @ Wout + bout
__global__ void prep3_kernel(const float* __restrict__ gg, const float* __restrict__ bb,
                             const float* __restrict__ Wout, const float* __restrict__ bout) {
    __shared__ float c[FD];
    int f = threadIdx.x;
    float m = g_stats[256 + f] * (1.0f / NN);
    float v = fmaxf(g_stats[320 + f] * (1.0f / NN) - m * m, 0.0f);
    float af = gg[f] * rsqrtf(v + BN_EPS);
    c[f] = bb[f] - m * af;
    g_Woutp[f * 2]     = af * Wout[f * 2];
    g_Woutp[f * 2 + 1] = af * Wout[f * 2 + 1];
    __syncthreads();
    if (f < 2) {
        float acc = bout[f];
        for (int i = 0; i < FD; i++) acc += c[i] * Wout[i * 2 + f];
        g_cb[f] = acc;
    }
}

// ---------------- out[g] = (gsum[g]/max(cnt,1) .* a3 + c3) @ Wout + bout
__global__ void final_kernel(float* __restrict__ out, const float* __restrict__ bout) {
    int g = blockIdx.x * blockDim.x + threadIdx.x;
    if (g >= NG) return;
    float cnt = g_gcnt[g];
    if (cnt > 0.0f) {
        float inv = 1.0f / cnt;
        float a0 = g_cb[0], a1 = g_cb[1];
#pragma unroll 8
        for (int f = 0; f < FD; f++) {
            float p = g_gsum[g * FD + f] * inv;
            a0 += p * g_Woutp[f * 2];
            a1 += p * g_Woutp[f * 2 + 1];
        }
        out[g * 2] = a0; out[g * 2 + 1] = a1;
    } else {
        out[g * 2] = bout[0]; out[g * 2 + 1] = bout[1];
    }
}

extern "C" void kernel_launch(void* const* d_in, const int* in_sizes, int n_in,
                              void* d_out, int out_size) {
    const float* x       = (const float*)d_in[0];
    const int*   ei      = (const int*)d_in[1];   // int32 or int64 (detected)
    const int*   batch   = (const int*)d_in[2];
    const float* bn_in_g = (const float*)d_in[3];
    const float* bn_in_b = (const float*)d_in[4];
    const float* W1      = (const float*)d_in[5];
    const float* b1      = (const float*)d_in[6];
    const float* g1      = (const float*)d_in[7];
    const float* be1     = (const float*)d_in[8];
    const float* W2      = (const float*)d_in[9];
    const float* b2      = (const float*)d_in[10];
    const float* g2      = (const float*)d_in[11];
    const float* be2     = (const float*)d_in[12];
    const float* Wout    = (const float*)d_in[13];
    const float* bout    = (const float*)d_in[14];
    float* out = (float*)d_out;

    detect_kernel<<<1, 256>>>(ei);
    init_kernel<<<(NN + 255) / 256, 256>>>();
    deg_kernel<<<(NE + 255) / 256, 256>>>(ei);
    rsqrt_kernel<<<(NN + 255) / 256, 256>>>();

    // CSR build (sorted by destination)
    scanA_kernel<<<SCAN_NB, 256>>>();
    scanB_kernel<<<1, 32>>>();
    scanC_kernel<<<SCAN_NB, 256>>>();
    place_kernel<<<(NE + 255) / 256, 256>>>(ei);

    // conv1: BN(x) folded into W1
    bn_stats_kernel<<<512, 256>>>(x, 0, x, 0, 0);
    prep_kernel<<<1, 64>>>(bn_in_g, bn_in_b, W1, 0);
    gemm_kernel<<<NN / 16, 256>>>(x, 0, x, 0);
    gather_kernel<<<(NN * 32 + 255) / 256, 256>>>();

    // conv2: BN(relu(agg1 + b1)) folded into W2
    bn_stats_kernel<<<512, 256>>>(x, 1, b1, 1, 128);
    prep_kernel<<<1, 64>>>(g1, be1, W2, 128);
    gemm_kernel<<<NN / 16, 256>>>(x, 1, b1, 1);
    gather_kernel<<<(NN * 32 + 255) / 256, 256>>>();

    // pool + BN3 folded into Wout
    pool_kernel<<<512, 256>>>(b2, batch);
    prep3_kernel<<<1, 64>>>(g2, be2, Wout, bout);
    final_kernel<<<4, 256>>>(out, bout);
}

// round 5
// speedup vs baseline: 1.6209x; 1.2906x over previous
#include <cuda_runtime.h>
#include <cuda_fp16.h>

#define NN 100000
#define NE 1280000
#define FD 64
#define NG 1000
#define BN_EPS 1e-5f
#define SCAN_CH 1024
#define SCAN_NB ((NN + SCAN_CH - 1) / SCAN_CH)   // 98

// ---------------- device scratch (allocation-free rule: __device__ globals) ----
__device__ int    g_deg[NN];
__device__ float  g_dinv[NN];
__device__ __half g_th[(size_t)NN * FD];      // transformed features (fp16 messages)
__device__ float  g_agg[(size_t)NN * FD];     // aggregated features (fp32)
__device__ float  g_stats[6 * FD];            // s1 ss1 | s2 ss2 | s3 ss3
__device__ float  g_gsum[NG * FD];
__device__ float  g_gcnt[NG];
__device__ int    g_is64;
// CSR sorted by destination; packed (src, norm-bits)
__device__ int    g_rowptr[NN + 1];
__device__ int    g_fill[NN];
__device__ int2   g_csr[NE];
__device__ int    g_bsum[SCAN_NB];
__device__ int    g_boff[SCAN_NB];

__device__ __forceinline__ unsigned pack_half2(float a, float b) {
    __half2 h = __floats2half2_rn(a, b);
    return (unsigned)__half_as_ushort(__low2half(h)) |
           ((unsigned)__half_as_ushort(__high2half(h)) << 16);
}

// ---------------- init + dtype detect (block 0 detects int64 via odd words==0)
__global__ void init_kernel(const int* __restrict__ ei) {
    int i = blockIdx.x * blockDim.x + threadIdx.x;
    if (i < NN) g_deg[i] = 0;
    if (i < 6 * FD) g_stats[i] = 0.0f;
    if (i < NG * FD) g_gsum[i] = 0.0f;
    if (i < NG) g_gcnt[i] = 0.0f;
    if (blockIdx.x == 0) {
        __shared__ int nz;
        if (threadIdx.x == 0) nz = 0;
        __syncthreads();
        int local = 0;
        for (int k = threadIdx.x; k < 4096; k += blockDim.x)
            if (ei[2 * k + 1] != 0) local = 1;
        if (local) nz = 1;
        __syncthreads();
        if (threadIdx.x == 0) g_is64 = (nz == 0) ? 1 : 0;
    }
}

__global__ void deg_kernel(const int* __restrict__ ei) {
    int e = blockIdx.x * blockDim.x + threadIdx.x;
    if (e >= NE) return;
    int c = g_is64 ? ei[2 * (NE + e)] : ei[NE + e];
    atomicAdd(&g_deg[c], 1);
}

// ---------------- rsqrt(deg+1) + per-chunk sums (scan level A) --------------
__global__ void rsqrt_scanA_kernel() {
    __shared__ int sh[256];
    int b = blockIdx.x, t = threadIdx.x;
    int base = b * SCAN_CH + t * 4;
    int s = 0;
#pragma unroll
    for (int k = 0; k < 4; k++) {
        int i = base + k;
        if (i < NN) {
            int d = g_deg[i];
            g_dinv[i] = rsqrtf((float)d + 1.0f);
            s += d;
        }
    }
    sh[t] = s;
    __syncthreads();
    for (int off = 128; off > 0; off >>= 1) {
        if (t < off) sh[t] += sh[t + off];
        __syncthreads();
    }
    if (t == 0) g_bsum[b] = sh[0];
}

__global__ void scanB_kernel() {
    if (threadIdx.x == 0) {
        int acc = 0;
        for (int b = 0; b < SCAN_NB; b++) { g_boff[b] = acc; acc += g_bsum[b]; }
        g_rowptr[NN] = acc;
    }
}

__global__ void scanC_kernel() {
    __shared__ int sh[257];
    int b = blockIdx.x, t = threadIdx.x;
    int base = b * SCAN_CH + t * 4;
    int v[4]; int s = 0;
#pragma unroll
    for (int k = 0; k < 4; k++) {
        int i = base + k;
        v[k] = (i < NN) ? g_deg[i] : 0;
        s += v[k];
    }
    sh[t + 1] = s;
    if (t == 0) sh[0] = 0;
    __syncthreads();
    for (int off = 1; off < 256; off <<= 1) {
        int val = (t + 1 > off) ? sh[t + 1 - off] : 0;
        __syncthreads();
        sh[t + 1] += val;
        __syncthreads();
    }
    int run = g_boff[b] + sh[t];
#pragma unroll
    for (int k = 0; k < 4; k++) {
        int i = base + k;
        if (i < NN) { g_rowptr[i] = run; g_fill[i] = run; run += v[k]; }
    }
}

__global__ void place_kernel(const int* __restrict__ ei) {
    int e = blockIdx.x * blockDim.x + threadIdx.x;
    if (e >= NE) return;
    int r, c;
    if (g_is64) { r = ei[2 * e]; c = ei[2 * (NE + e)]; }
    else        { r = ei[e];     c = ei[NE + e]; }
    int pos = atomicAdd(&g_fill[c], 1);
    float nrm = g_dinv[r] * g_dinv[c];
    g_csr[pos] = make_int2(r, __float_as_int(nrm));
}

// ---------------- BN stats for layer-1 input x ------------------------------
__global__ void bn_stats_x_kernel(const float* __restrict__ x) {
    int f   = threadIdx.x & 63;
    int sub = threadIdx.x >> 6;
    float s = 0.0f, ss = 0.0f;
    for (int n = blockIdx.x * 4 + sub; n < NN; n += gridDim.x * 4) {
        float v = x[(size_t)n * FD + f];
        s += v; ss += v * v;
    }
    atomicAdd(&g_stats[f], s);
    atomicAdd(&g_stats[64 + f], ss);
}

// ---------------- GEMM with fused BN fold:  t = prologue(in) @ (diag(a)W) + c@W
// prologue = relu(in + bias) if dorelu.  Output fp16.  32 rows/block.
__global__ void gemm_kernel(const float* __restrict__ xin, int use_agg,
                            const float* __restrict__ bias, int dorelu,
                            const float* __restrict__ gg, const float* __restrict__ bb,
                            const float* __restrict__ W, int soff) {
    __shared__ float sIn[32 * 66];          // padded rows (bank-conflict free)
    __shared__ float sW[FD * FD];
    __shared__ float sA[FD], sC[FD], sCrow[FD];
    const float* __restrict__ src = use_agg ? g_agg : xin;
    int tid = threadIdx.x;

    // raw W into smem + BN fold coefficients
    for (int i = tid; i < FD * FD; i += 256) sW[i] = W[i];
    if (tid < FD) {
        float m = g_stats[soff + tid] * (1.0f / NN);
        float v = fmaxf(g_stats[soff + 64 + tid] * (1.0f / NN) - m * m, 0.0f);
        float af = gg[tid] * rsqrtf(v + BN_EPS);
        sA[tid] = af;
        sC[tid] = bb[tid] - m * af;
    }
    __syncthreads();

    // crow (registers, raw sW) overlapped with sIn load
    int base = blockIdx.x * 32;
    for (int i = tid; i < 32 * FD; i += 256) {
        int r = i >> 6, k = i & 63;
        float v = src[(size_t)(base + r) * FD + k];
        if (dorelu) v = fmaxf(v + bias[k], 0.0f);
        sIn[r * 66 + k] = v;
    }
    float cr = 0.0f;
    if (tid < FD) {
        for (int i = 0; i < FD; i++) cr += sC[i] * sW[i * FD + tid];
    }
    __syncthreads();

    // scale sW in place, publish crow
    for (int i = tid; i < FD * FD; i += 256) sW[i] *= sA[i >> 6];
    if (tid < FD) sCrow[tid] = cr;
    __syncthreads();

    int rp = tid >> 4, tc = tid & 15;
    int r0 = rp * 2, r1 = r0 + 1;
    float4 a0 = make_float4(0.f, 0.f, 0.f, 0.f);
    float4 a1 = make_float4(0.f, 0.f, 0.f, 0.f);
    const float4* sW4 = (const float4*)sW;
#pragma unroll
    for (int k = 0; k < FD; k++) {
        float x0 = sIn[r0 * 66 + k];
        float x1 = sIn[r1 * 66 + k];
        float4 w = sW4[k * 16 + tc];
        a0.x += x0 * w.x; a0.y += x0 * w.y; a0.z += x0 * w.z; a0.w += x0 * w.w;
        a1.x += x1 * w.x; a1.y += x1 * w.y; a1.z += x1 * w.z; a1.w += x1 * w.w;
    }
    float4 crw = ((const float4*)sCrow)[tc];
    a0.x += crw.x; a0.y += crw.y; a0.z += crw.z; a0.w += crw.w;
    a1.x += crw.x; a1.y += crw.y; a1.z += crw.z; a1.w += crw.w;

    uint2 u0 = make_uint2(pack_half2(a0.x, a0.y), pack_half2(a0.z, a0.w));
    uint2 u1 = make_uint2(pack_half2(a1.x, a1.y), pack_half2(a1.z, a1.w));
    ((uint2*)g_th)[(size_t)(base + r0) * 16 + tc] = u0;
    ((uint2*)g_th)[(size_t)(base + r1) * 16 + tc] = u1;
}

// ---------------- CSR gather conv: warp/node, lane = 2 feats, fp16 messages.
// Optional epilogue: BN stats of relu(agg + bias) via block reduction.
__global__ void gather_kernel(int do_stats, const float* __restrict__ bias, int soff) {
    __shared__ float sStat[128];
    int tid  = threadIdx.x;
    int lane = tid & 31;
    if (do_stats && tid < 128) sStat[tid] = 0.0f;

    int n = (blockIdx.x * blockDim.x + tid) >> 5;   // 16 nodes per 512-thread block
    const __half2* th2 = (const __half2*)g_th;
    float d = g_dinv[n];
    float s = d * d;
    float2 acc = __half22float2(th2[(size_t)n * 32 + lane]);
    acc.x *= s; acc.y *= s;

    int j = g_rowptr[n], end = g_rowptr[n + 1];
    for (; j + 2 <= end; j += 2) {
        int2 p0 = g_csr[j];
        int2 p1 = g_csr[j + 1];
        float2 v0 = __half22float2(th2[(size_t)p0.x * 32 + lane]);
        float2 v1 = __half22float2(th2[(size_t)p1.x * 32 + lane]);
        float w0 = __int_as_float(p0.y), w1 = __int_as_float(p1.y);
        acc.x += v0.x * w0 + v1.x * w1;
        acc.y += v0.y * w0 + v1.y * w1;
    }
    if (j < end) {
        int2 p = g_csr[j];
        float2 v = __half22float2(th2[(size_t)p.x * 32 + lane]);
        float w = __int_as_float(p.y);
        acc.x += v.x * w;
        acc.y += v.y * w;
    }
    ((float2*)g_agg)[(size_t)n * 32 + lane] = acc;

    if (do_stats) {
        float2 bb = ((const float2*)bias)[lane];
        float y0 = fmaxf(acc.x + bb.x, 0.0f);
        float y1 = fmaxf(acc.y + bb.y, 0.0f);
        __syncthreads();             // zero-fill visible, all accs done
        atomicAdd(&sStat[2 * lane],      y0);
        atomicAdd(&sStat[2 * lane + 1],  y1);
        atomicAdd(&sStat[64 + 2 * lane],     y0 * y0);
        atomicAdd(&sStat[64 + 2 * lane + 1], y1 * y1);
        __syncthreads();
        if (tid < 128) atomicAdd(&g_stats[soff + tid], sStat[tid]);
    }
}

// ---------------- pool: y=relu(agg+b2); BN3 stats + per-graph sums (batch sorted)
__global__ void pool_kernel(const float* __restrict__ bias, const int* __restrict__ batch) {
    int f   = threadIdx.x & 63;
    int sub = threadIdx.x >> 6;
    int is64 = g_is64;
    float bs = bias[f];
    const int chunk = 196;                 // 512 blocks * 196 >= NN
    const int subc  = 49;
    int start = blockIdx.x * chunk + sub * subc;
    int stop  = min(start + subc, NN);
    float s = 0.0f, ss = 0.0f;
    int   cur = -1;
    float gv = 0.0f, gc = 0.0f;
    for (int n = start; n < stop; n++) {
        int b = is64 ? batch[2 * n] : batch[n];
        if (b != cur) {
            if (cur >= 0) {
                atomicAdd(&g_gsum[cur * FD + f], gv);
                if (f == 0) atomicAdd(&g_gcnt[cur], gc);
            }
            cur = b; gv = 0.0f; gc = 0.0f;
        }
        float v = fmaxf(g_agg[(size_t)n * FD + f] + bs, 0.0f);
        s += v; ss += v * v;
        gv += v; gc += 1.0f;
    }
    if (cur >= 0) {
        atomicAdd(&g_gsum[cur * FD + f], gv);
        if (f == 0) atomicAdd(&g_gcnt[cur], gc);
    }
    atomicAdd(&g_stats[256 + f], s);
    atomicAdd(&g_stats[320 + f], ss);
}

// ---------------- final: fold BN3 into Wout, emit [NG, 2] --------------------
__global__ void final_kernel(const float* __restrict__ gg, const float* __restrict__ bb,
                             const float* __restrict__ Wout, const float* __restrict__ bout,
                             float* __restrict__ out) {
    __shared__ float sWp[FD * 2];
    __shared__ float sc[FD];
    __shared__ float scb[2];
    int tid = threadIdx.x;
    if (tid < FD) {
        float m = g_stats[256 + tid] * (1.0f / NN);
        float v = fmaxf(g_stats[320 + tid] * (1.0f / NN) - m * m, 0.0f);
        float af = gg[tid] * rsqrtf(v + BN_EPS);
        sc[tid] = bb[tid] - m * af;
        sWp[tid * 2]     = af * Wout[tid * 2];
        sWp[tid * 2 + 1] = af * Wout[tid * 2 + 1];
    }
    __syncthreads();
    if (tid < 2) {
        float acc = bout[tid];
        for (int i = 0; i < FD; i++) acc += sc[i] * Wout[i * 2 + tid];
        scb[tid] = acc;
    }
    __syncthreads();
    int g = blockIdx.x * blockDim.x + tid;
    if (g >= NG) return;
    float cnt = g_gcnt[g];
    if (cnt > 0.0f) {
        float inv = 1.0f / cnt;
        float a0 = scb[0], a1 = scb[1];
#pragma unroll 8
        for (int f = 0; f < FD; f++) {
            float p = g_gsum[g * FD + f] * inv;
            a0 += p * sWp[f * 2];
            a1 += p * sWp[f * 2 + 1];
        }
        out[g * 2] = a0; out[g * 2 + 1] = a1;
    } else {
        out[g * 2] = bout[0]; out[g * 2 + 1] = bout[1];
    }
}

extern "C" void kernel_launch(void* const* d_in, const int* in_sizes, int n_in,
                              void* d_out, int out_size) {
    const float* x       = (const float*)d_in[0];
    const int*   ei      = (const int*)d_in[1];
    const int*   batch   = (const int*)d_in[2];
    const float* bn_in_g = (const float*)d_in[3];
    const float* bn_in_b = (const float*)d_in[4];
    const float* W1      = (const float*)d_in[5];
    const float* b1      = (const float*)d_in[6];
    const float* g1      = (const float*)d_in[7];
    const float* be1     = (const float*)d_in[8];
    const float* W2      = (const float*)d_in[9];
    const float* b2      = (const float*)d_in[10];
    const float* g2      = (const float*)d_in[11];
    const float* be2     = (const float*)d_in[12];
    const float* Wout    = (const float*)d_in[13];
    const float* bout    = (const float*)d_in[14];
    float* out = (float*)d_out;

    init_kernel<<<(NN + 255) / 256, 256>>>(ei);
    deg_kernel<<<(NE + 255) / 256, 256>>>(ei);
    bn_stats_x_kernel<<<512, 256>>>(x);
    gemm_kernel<<<NN / 32, 256>>>(x, 0, x, 0, bn_in_g, bn_in_b, W1, 0);   // conv1 transform
    rsqrt_scanA_kernel<<<SCAN_NB, 256>>>();
    scanB_kernel<<<1, 32>>>();
    scanC_kernel<<<SCAN_NB, 256>>>();
    place_kernel<<<(NE + 255) / 256, 256>>>(ei);
    gather_kernel<<<NN / 16, 512>>>(1, b1, 128);                          // conv1 agg + BN2 stats
    gemm_kernel<<<NN / 32, 256>>>(x, 1, b1, 1, g1, be1, W2, 128);         // conv2 transform
    gather_kernel<<<NN / 16, 512>>>(0, b1, 0);                            // conv2 agg
    pool_kernel<<<512, 256>>>(b2, batch);
    final_kernel<<<4, 256>>>(g2, be2, Wout, bout, out);
}

// round 6
// speedup vs baseline: 1.7921x; 1.1056x over previous
#include <cuda_runtime.h>
#include <cuda_fp16.h>

#define NN 100000
#define NE 1280000
#define FD 64
#define NG 1000
#define BN_EPS 1e-5f
#define SCAN_CH 1024
#define SCAN_NB ((NN + SCAN_CH - 1) / SCAN_CH)   // 98

// ---------------- device scratch (allocation-free rule: __device__ globals) ----
__device__ int    g_deg[NN];
__device__ float  g_dinv[NN];
__device__ __half g_th[(size_t)NN * FD];      // transformed features (fp16 messages)
__device__ float  g_agg[(size_t)NN * FD];     // aggregated features (fp32)
__device__ float  g_stats[6 * FD];            // s1 ss1 | s2 ss2 | s3 ss3
__device__ float  g_gsum[NG * FD];
__device__ float  g_gcnt[NG];
__device__ int    g_is64;
// CSR sorted by destination; packed (src, norm-bits)
__device__ int    g_rowptr[NN + 1];
__device__ int    g_fill[NN];
__device__ int2   g_csr[NE];
__device__ int    g_bsum[SCAN_NB];
__device__ int    g_boff[SCAN_NB];

__device__ __forceinline__ unsigned pack_half2(float a, float b) {
    __half2 h = __floats2half2_rn(a, b);
    return (unsigned)__half_as_ushort(__low2half(h)) |
           ((unsigned)__half_as_ushort(__high2half(h)) << 16);
}

// ---------------- init + dtype detect (block 0 detects int64 via odd words==0)
__global__ void init_kernel(const int* __restrict__ ei) {
    int i = blockIdx.x * blockDim.x + threadIdx.x;
    if (i < NN) g_deg[i] = 0;
    if (i < 6 * FD) g_stats[i] = 0.0f;
    if (i < NG * FD) g_gsum[i] = 0.0f;
    if (i < NG) g_gcnt[i] = 0.0f;
    if (blockIdx.x == 0) {
        __shared__ int nz;
        if (threadIdx.x == 0) nz = 0;
        __syncthreads();
        int local = 0;
        for (int k = threadIdx.x; k < 4096; k += blockDim.x)
            if (ei[2 * k + 1] != 0) local = 1;
        if (local) nz = 1;
        __syncthreads();
        if (threadIdx.x == 0) g_is64 = (nz == 0) ? 1 : 0;
    }
}

__global__ void deg_kernel(const int* __restrict__ ei) {
    int e = blockIdx.x * blockDim.x + threadIdx.x;
    if (e >= NE) return;
    int c = g_is64 ? ei[2 * (NE + e)] : ei[NE + e];
    atomicAdd(&g_deg[c], 1);
}

// ---------------- rsqrt(deg+1) + per-chunk sums (scan level A) --------------
__global__ void rsqrt_scanA_kernel() {
    __shared__ int sh[256];
    int b = blockIdx.x, t = threadIdx.x;
    int base = b * SCAN_CH + t * 4;
    int s = 0;
#pragma unroll
    for (int k = 0; k < 4; k++) {
        int i = base + k;
        if (i < NN) {
            int d = g_deg[i];
            g_dinv[i] = rsqrtf((float)d + 1.0f);
            s += d;
        }
    }
    sh[t] = s;
    __syncthreads();
    for (int off = 128; off > 0; off >>= 1) {
        if (t < off) sh[t] += sh[t + off];
        __syncthreads();
    }
    if (t == 0) g_bsum[b] = sh[0];
}

__global__ void scanB_kernel() {
    if (threadIdx.x == 0) {
        int acc = 0;
        for (int b = 0; b < SCAN_NB; b++) { g_boff[b] = acc; acc += g_bsum[b]; }
        g_rowptr[NN] = acc;
    }
}

__global__ void scanC_kernel() {
    __shared__ int sh[257];
    int b = blockIdx.x, t = threadIdx.x;
    int base = b * SCAN_CH + t * 4;
    int v[4]; int s = 0;
#pragma unroll
    for (int k = 0; k < 4; k++) {
        int i = base + k;
        v[k] = (i < NN) ? g_deg[i] : 0;
        s += v[k];
    }
    sh[t + 1] = s;
    if (t == 0) sh[0] = 0;
    __syncthreads();
    for (int off = 1; off < 256; off <<= 1) {
        int val = (t + 1 > off) ? sh[t + 1 - off] : 0;
        __syncthreads();
        sh[t + 1] += val;
        __syncthreads();
    }
    int run = g_boff[b] + sh[t];
#pragma unroll
    for (int k = 0; k < 4; k++) {
        int i = base + k;
        if (i < NN) { g_rowptr[i] = run; g_fill[i] = run; run += v[k]; }
    }
}

__global__ void place_kernel(const int* __restrict__ ei) {
    int e = blockIdx.x * blockDim.x + threadIdx.x;
    if (e >= NE) return;
    int r, c;
    if (g_is64) { r = ei[2 * e]; c = ei[2 * (NE + e)]; }
    else        { r = ei[e];     c = ei[NE + e]; }
    int pos = atomicAdd(&g_fill[c], 1);
    float nrm = g_dinv[r] * g_dinv[c];
    g_csr[pos] = make_int2(r, __float_as_int(nrm));
}

// ---------------- BN stats for layer-1 input x ------------------------------
__global__ void bn_stats_x_kernel(const float* __restrict__ x) {
    int f   = threadIdx.x & 63;
    int sub = threadIdx.x >> 6;
    float s = 0.0f, ss = 0.0f;
    for (int n = blockIdx.x * 4 + sub; n < NN; n += gridDim.x * 4) {
        float v = x[(size_t)n * FD + f];
        s += v; ss += v * v;
    }
    atomicAdd(&g_stats[f], s);
    atomicAdd(&g_stats[64 + f], ss);
}

// ---------------- GEMM with fused BN fold:  t = prologue(in) @ (diag(a)W) + c@W
// prologue = relu(in + bias) if dorelu.  Output fp16.
// 64 rows/block, 256 threads, 4x4 register blocking (FFMA-bound, not LDS-bound).
__global__ void gemm_kernel(const float* __restrict__ xin, int use_agg,
                            const float* __restrict__ bias, int dorelu,
                            const float* __restrict__ gg, const float* __restrict__ bb,
                            const float* __restrict__ W, int soff) {
    __shared__ float sIn[64 * 68];          // pad 68: float4-aligned rows, conflict-free
    __shared__ float sW[FD * FD];
    __shared__ float sA[FD], sC[FD], sCrow[FD];
    const float* __restrict__ src = use_agg ? g_agg : xin;
    int tid = threadIdx.x;

    // raw W into smem + BN fold coefficients
    for (int i = tid; i < FD * FD; i += 256) sW[i] = W[i];
    if (tid < FD) {
        float m = g_stats[soff + tid] * (1.0f / NN);
        float v = fmaxf(g_stats[soff + 64 + tid] * (1.0f / NN) - m * m, 0.0f);
        float af = gg[tid] * rsqrtf(v + BN_EPS);
        sA[tid] = af;
        sC[tid] = bb[tid] - m * af;
    }
    __syncthreads();

    // input tile load (overlapped with crow compute below)
    int base = blockIdx.x * 64;
    int nrows = min(64, NN - base);
    for (int i = tid; i < 64 * 16; i += 256) {
        int r = i >> 4, kc = i & 15;
        float4 v = make_float4(0.f, 0.f, 0.f, 0.f);
        if (r < nrows) {
            v = ((const float4*)src)[(size_t)(base + r) * 16 + kc];
            if (dorelu) {
                float4 bv = ((const float4*)bias)[kc];
                v.x = fmaxf(v.x + bv.x, 0.0f);
                v.y = fmaxf(v.y + bv.y, 0.0f);
                v.z = fmaxf(v.z + bv.z, 0.0f);
                v.w = fmaxf(v.w + bv.w, 0.0f);
            }
        }
        *((float4*)&sIn[r * 68 + kc * 4]) = v;
    }
    float cr = 0.0f;
    if (tid < FD) {
        for (int i = 0; i < FD; i++) cr += sC[i] * sW[i * FD + tid];
    }
    __syncthreads();

    // scale sW in place, publish crow
    for (int i = tid; i < FD * FD; i += 256) sW[i] *= sA[i >> 6];
    if (tid < FD) sCrow[tid] = cr;
    __syncthreads();

    int rp = tid >> 4, tc = tid & 15;      // rp: 4-row group, tc: 4-col group
    int rbase = rp * 4;
    float4 acc0 = make_float4(0.f, 0.f, 0.f, 0.f);
    float4 acc1 = make_float4(0.f, 0.f, 0.f, 0.f);
    float4 acc2 = make_float4(0.f, 0.f, 0.f, 0.f);
    float4 acc3 = make_float4(0.f, 0.f, 0.f, 0.f);
    const float4* sW4 = (const float4*)sW;
#pragma unroll
    for (int k = 0; k < FD; k++) {
        float4 w = sW4[k * 16 + tc];
        float x0 = sIn[(rbase + 0) * 68 + k];
        float x1 = sIn[(rbase + 1) * 68 + k];
        float x2 = sIn[(rbase + 2) * 68 + k];
        float x3 = sIn[(rbase + 3) * 68 + k];
        acc0.x += x0 * w.x; acc0.y += x0 * w.y; acc0.z += x0 * w.z; acc0.w += x0 * w.w;
        acc1.x += x1 * w.x; acc1.y += x1 * w.y; acc1.z += x1 * w.z; acc1.w += x1 * w.w;
        acc2.x += x2 * w.x; acc2.y += x2 * w.y; acc2.z += x2 * w.z; acc2.w += x2 * w.w;
        acc3.x += x3 * w.x; acc3.y += x3 * w.y; acc3.z += x3 * w.z; acc3.w += x3 * w.w;
    }
    float4 crw = ((const float4*)sCrow)[tc];
    acc0.x += crw.x; acc0.y += crw.y; acc0.z += crw.z; acc0.w += crw.w;
    acc1.x += crw.x; acc1.y += crw.y; acc1.z += crw.z; acc1.w += crw.w;
    acc2.x += crw.x; acc2.y += crw.y; acc2.z += crw.z; acc2.w += crw.w;
    acc3.x += crw.x; acc3.y += crw.y; acc3.z += crw.z; acc3.w += crw.w;

    uint2* th2 = (uint2*)g_th;
    if (rbase + 0 < nrows) th2[(size_t)(base + rbase + 0) * 16 + tc] = make_uint2(pack_half2(acc0.x, acc0.y), pack_half2(acc0.z, acc0.w));
    if (rbase + 1 < nrows) th2[(size_t)(base + rbase + 1) * 16 + tc] = make_uint2(pack_half2(acc1.x, acc1.y), pack_half2(acc1.z, acc1.w));
    if (rbase + 2 < nrows) th2[(size_t)(base + rbase + 2) * 16 + tc] = make_uint2(pack_half2(acc2.x, acc2.y), pack_half2(acc2.z, acc2.w));
    if (rbase + 3 < nrows) th2[(size_t)(base + rbase + 3) * 16 + tc] = make_uint2(pack_half2(acc3.x, acc3.y), pack_half2(acc3.z, acc3.w));
}

// ---------------- CSR gather conv: warp/node, lane = 2 feats, fp16 messages.
// Optional epilogue: BN stats of relu(agg + bias) via block reduction.
__global__ void gather_kernel(int do_stats, const float* __restrict__ bias, int soff) {
    __shared__ float sStat[128];
    int tid  = threadIdx.x;
    int lane = tid & 31;
    if (do_stats && tid < 128) sStat[tid] = 0.0f;

    int n = (blockIdx.x * blockDim.x + tid) >> 5;   // 16 nodes per 512-thread block
    const __half2* th2 = (const __half2*)g_th;
    float d = g_dinv[n];
    float s = d * d;
    float2 acc = __half22float2(th2[(size_t)n * 32 + lane]);
    acc.x *= s; acc.y *= s;

    int j = g_rowptr[n], end = g_rowptr[n + 1];
    for (; j + 2 <= end; j += 2) {
        int2 p0 = g_csr[j];
        int2 p1 = g_csr[j + 1];
        float2 v0 = __half22float2(th2[(size_t)p0.x * 32 + lane]);
        float2 v1 = __half22float2(th2[(size_t)p1.x * 32 + lane]);
        float w0 = __int_as_float(p0.y), w1 = __int_as_float(p1.y);
        acc.x += v0.x * w0 + v1.x * w1;
        acc.y += v0.y * w0 + v1.y * w1;
    }
    if (j < end) {
        int2 p = g_csr[j];
        float2 v = __half22float2(th2[(size_t)p.x * 32 + lane]);
        float w = __int_as_float(p.y);
        acc.x += v.x * w;
        acc.y += v.y * w;
    }
    ((float2*)g_agg)[(size_t)n * 32 + lane] = acc;

    if (do_stats) {
        float2 bb = ((const float2*)bias)[lane];
        float y0 = fmaxf(acc.x + bb.x, 0.0f);
        float y1 = fmaxf(acc.y + bb.y, 0.0f);
        __syncthreads();             // zero-fill visible, all accs done
        atomicAdd(&sStat[2 * lane],      y0);
        atomicAdd(&sStat[2 * lane + 1],  y1);
        atomicAdd(&sStat[64 + 2 * lane],     y0 * y0);
        atomicAdd(&sStat[64 + 2 * lane + 1], y1 * y1);
        __syncthreads();
        if (tid < 128) atomicAdd(&g_stats[soff + tid], sStat[tid]);
    }
}

// ---------------- pool: y=relu(agg+b2); BN3 stats + per-graph sums (batch sorted)
__global__ void pool_kernel(const float* __restrict__ bias, const int* __restrict__ batch) {
    int f   = threadIdx.x & 63;
    int sub = threadIdx.x >> 6;
    int is64 = g_is64;
    float bs = bias[f];
    const int chunk = 196;                 // 512 blocks * 196 >= NN
    const int subc  = 49;
    int start = blockIdx.x * chunk + sub * subc;
    int stop  = min(start + subc, NN);
    float s = 0.0f, ss = 0.0f;
    int   cur = -1;
    float gv = 0.0f, gc = 0.0f;
    for (int n = start; n < stop; n++) {
        int b = is64 ? batch[2 * n] : batch[n];
        if (b != cur) {
            if (cur >= 0) {
                atomicAdd(&g_gsum[cur * FD + f], gv);
                if (f == 0) atomicAdd(&g_gcnt[cur], gc);
            }
            cur = b; gv = 0.0f; gc = 0.0f;
        }
        float v = fmaxf(g_agg[(size_t)n * FD + f] + bs, 0.0f);
        s += v; ss += v * v;
        gv += v; gc += 1.0f;
    }
    if (cur >= 0) {
        atomicAdd(&g_gsum[cur * FD + f], gv);
        if (f == 0) atomicAdd(&g_gcnt[cur], gc);
    }
    atomicAdd(&g_stats[256 + f], s);
    atomicAdd(&g_stats[320 + f], ss);
}

// ---------------- final: fold BN3 into Wout, emit [NG, 2] --------------------
__global__ void final_kernel(const float* __restrict__ gg, const float* __restrict__ bb,
                             const float* __restrict__ Wout, const float* __restrict__ bout,
                             float* __restrict__ out) {
    __shared__ float sWp[FD * 2];
    __shared__ float sc[FD];
    __shared__ float scb[2];
    int tid = threadIdx.x;
    if (tid < FD) {
        float m = g_stats[256 + tid] * (1.0f / NN);
        float v = fmaxf(g_stats[320 + tid] * (1.0f / NN) - m * m, 0.0f);
        float af = gg[tid] * rsqrtf(v + BN_EPS);
        sc[tid] = bb[tid] - m * af;
        sWp[tid * 2]     = af * Wout[tid * 2];
        sWp[tid * 2 + 1] = af * Wout[tid * 2 + 1];
    }
    __syncthreads();
    if (tid < 2) {
        float acc = bout[tid];
        for (int i = 0; i < FD; i++) acc += sc[i] * Wout[i * 2 + tid];
        scb[tid] = acc;
    }
    __syncthreads();
    int g = blockIdx.x * blockDim.x + tid;
    if (g >= NG) return;
    float cnt = g_gcnt[g];
    if (cnt > 0.0f) {
        float inv = 1.0f / cnt;
        float a0 = scb[0], a1 = scb[1];
#pragma unroll 8
        for (int f = 0; f < FD; f++) {
            float p = g_gsum[g * FD + f] * inv;
            a0 += p * sWp[f * 2];
            a1 += p * sWp[f * 2 + 1];
        }
        out[g * 2] = a0; out[g * 2 + 1] = a1;
    } else {
        out[g * 2] = bout[0]; out[g * 2 + 1] = bout[1];
    }
}

extern "C" void kernel_launch(void* const* d_in, const int* in_sizes, int n_in,
                              void* d_out, int out_size) {
    const float* x       = (const float*)d_in[0];
    const int*   ei      = (const int*)d_in[1];
    const int*   batch   = (const int*)d_in[2];
    const float* bn_in_g = (const float*)d_in[3];
    const float* bn_in_b = (const float*)d_in[4];
    const float* W1      = (const float*)d_in[5];
    const float* b1      = (const float*)d_in[6];
    const float* g1      = (const float*)d_in[7];
    const float* be1     = (const float*)d_in[8];
    const float* W2      = (const float*)d_in[9];
    const float* b2      = (const float*)d_in[10];
    const float* g2      = (const float*)d_in[11];
    const float* be2     = (const float*)d_in[12];
    const float* Wout    = (const float*)d_in[13];
    const float* bout    = (const float*)d_in[14];
    float* out = (float*)d_out;

    const int GEMM_GRID = (NN + 63) / 64;   // 1563

    init_kernel<<<(NN + 255) / 256, 256>>>(ei);
    deg_kernel<<<(NE + 255) / 256, 256>>>(ei);
    bn_stats_x_kernel<<<512, 256>>>(x);
    gemm_kernel<<<GEMM_GRID, 256>>>(x, 0, x, 0, bn_in_g, bn_in_b, W1, 0); // conv1 transform
    rsqrt_scanA_kernel<<<SCAN_NB, 256>>>();
    scanB_kernel<<<1, 32>>>();
    scanC_kernel<<<SCAN_NB, 256>>>();
    place_kernel<<<(NE + 255) / 256, 256>>>(ei);
    gather_kernel<<<NN / 16, 512>>>(1, b1, 128);                          // conv1 agg + BN2 stats
    gemm_kernel<<<GEMM_GRID, 256>>>(x, 1, b1, 1, g1, be1, W2, 128);       // conv2 transform
    gather_kernel<<<NN / 16, 512>>>(0, b1, 0);                            // conv2 agg
    pool_kernel<<<512, 256>>>(b2, batch);
    final_kernel<<<4, 256>>>(g2, be2, Wout, bout, out);
}